// round 3
// baseline (speedup 1.0000x reference)
#include <cuda_runtime.h>

#define T 48
#define E 32
#define C0 64
#define C1 64
#define H1 256
#define H2 128
#define NPRED 12
#define SEQS (16 * 2048)

typedef unsigned long long u64;

__device__ __forceinline__ u64 pk2(float lo, float hi) {
    u64 r; asm("mov.b64 %0,{%1,%2};" : "=l"(r) : "f"(lo), "f"(hi)); return r;
}
__device__ __forceinline__ u64 dupf(float v) {
    u64 r; asm("mov.b64 %0,{%1,%1};" : "=l"(r) : "f"(v)); return r;
}
__device__ __forceinline__ void fma2(u64& d, u64 a, u64 b) {
    asm("fma.rn.f32x2 %0, %1, %2, %0;" : "+l"(d) : "l"(a), "l"(b));
}
__device__ __forceinline__ float2 unpk(u64 v) {
    float2 f; asm("mov.b64 {%0,%1},%2;" : "=f"(f.x), "=f"(f.y) : "l"(v)); return f;
}

// scratch: attention context last row per sequence
__device__ float g_last[SEQS * C1];

// ---------------- Kernel A ----------------
// 2 sequences per CTA-iteration (96 rows). Packed f32x2 FMA, col-pair packing.
// smem layout (float offsets), all even:
//  sWin 0      (2048)
//  sWc  2048   (12288)
//  sWq  14336  (4096)
//  sWk  18432  (4096)
//  sWv  22528  (4096)
//  sB   26624  (320)
//  sx   26944  (96*34  = 3264)   stride 34
//  sh   30208  (100*66 = 6600)   stride 66, padded rows 0,49,50,99 = 0
//  shc  36808  (96*66  = 6336)   stride 66
//  sk   43144  (96*66  = 6336)
//  sv   49480  (96*66  = 6336)
//  sq   55816  (128)
//  ss   55944  (96)
#define SMEM_A_FLOATS 56040

__global__ void __launch_bounds__(256, 1)
kernelA(const float* __restrict__ x,
        const float* __restrict__ Win, const float* __restrict__ bin,
        const float* __restrict__ Wc,  const float* __restrict__ bc,
        const float* __restrict__ Wq,  const float* __restrict__ bq,
        const float* __restrict__ Wk,  const float* __restrict__ bk,
        const float* __restrict__ Wv,  const float* __restrict__ bv)
{
    extern __shared__ float sm[];
    float* sWin = sm;
    float* sWc  = sm + 2048;
    float* sWq  = sm + 14336;
    float* sWk  = sm + 18432;
    float* sWv  = sm + 22528;
    float* sB   = sm + 26624;
    float* sx   = sm + 26944;
    float* sh   = sm + 30208;
    float* shc  = sm + 36808;
    float* sk   = sm + 43144;
    float* sv   = sm + 49480;
    float* sq   = sm + 55816;
    float* ss   = sm + 55944;

    const int tid = threadIdx.x;

    // stage weights once per CTA
    for (int i = tid; i < 2048; i += 256) sWin[i] = Win[i];
    for (int i = tid; i < 12288; i += 256) sWc[i] = Wc[i];
    for (int i = tid; i < 4096; i += 256) {
        sWq[i] = Wq[i]; sWk[i] = Wk[i]; sWv[i] = Wv[i];
    }
    if (tid < 64) {
        sB[tid]       = bin[tid];
        sB[64 + tid]  = bc[tid];
        sB[128 + tid] = bq[tid];
        sB[192 + tid] = bk[tid];
        sB[256 + tid] = bv[tid];
    }
    // zero pad rows of sh (rows 0, 49, 50, 99)
    {
        const int padr[4] = {0, 49, 50, 99};
        int p = padr[tid >> 6], c = tid & 63;
        sh[p * 66 + c] = 0.f;
    }
    __syncthreads();

    const int c8   = (tid & 7) * 8;   // 8-column base (even)
    const int rg   = tid >> 3;        // 0..31 : rows rg, rg+32, rg+64
    const int lane = tid & 31;
    const int warp = tid >> 5;

    // per-thread row indices
    int rr[3], pb[3];
    #pragma unroll
    for (int j = 0; j < 3; j++) {
        rr[j] = rg + 32 * j;                         // global row 0..95
        int pr = rr[j] + 1 + 2 * (rr[j] >= 48);      // padded h row
        pb[j] = pr - 1;                              // conv window base
    }

    for (int pair = blockIdx.x; pair < SEQS / 2; pair += gridDim.x) {
        const int seq0 = pair * 2;

        // ---- 1) stage x for 2 seqs: 96 rows x 32, stride 34 ----
        {
            const float4* xg = (const float4*)(x + (size_t)seq0 * (T * E));
            #pragma unroll
            for (int k = 0; k < 3; k++) {
                int idx = tid + k * 256;             // 0..767
                float4 v = xg[idx];
                int row = idx >> 3, e4 = idx & 7;
                u64* d = (u64*)(sx + row * 34 + e4 * 4);
                d[0] = pk2(v.x, v.y);
                d[1] = pk2(v.z, v.w);
            }
        }
        __syncthreads();

        // ---- 2) in-projection: h[row][c] = x[row]·Win[:,c] + bin ----
        {
            u64 acc[3][4];
            const u64* bb = (const u64*)(sB + c8);
            #pragma unroll
            for (int j = 0; j < 3; j++)
                #pragma unroll
                for (int k = 0; k < 4; k++) acc[j][k] = bb[k];
            #pragma unroll 8
            for (int e = 0; e < E; e++) {
                const ulonglong2* wr = (const ulonglong2*)(sWin + e * C0 + c8);
                ulonglong2 wa = wr[0], wb2 = wr[1];
                #pragma unroll
                for (int j = 0; j < 3; j++) {
                    u64 xv = dupf(sx[rr[j] * 34 + e]);
                    fma2(acc[j][0], xv, wa.x); fma2(acc[j][1], xv, wa.y);
                    fma2(acc[j][2], xv, wb2.x); fma2(acc[j][3], xv, wb2.y);
                }
            }
            #pragma unroll
            for (int j = 0; j < 3; j++) {
                u64* d = (u64*)(sh + (pb[j] + 1) * 66 + c8);
                #pragma unroll
                for (int k = 0; k < 4; k++) d[k] = acc[j][k];
            }
        }
        __syncthreads();

        // ---- 3) conv(k=3, pad=1) + ReLU ----
        {
            u64 acc[3][4];
            const u64* bb = (const u64*)(sB + 64 + c8);
            #pragma unroll
            for (int j = 0; j < 3; j++)
                #pragma unroll
                for (int k = 0; k < 4; k++) acc[j][k] = bb[k];
            #pragma unroll
            for (int dt = 0; dt < 3; dt++) {
                const float* wbase = sWc + dt * C0 * C1 + c8;
                #pragma unroll 8
                for (int ci = 0; ci < C0; ci++) {
                    const ulonglong2* wr = (const ulonglong2*)(wbase + ci * C1);
                    ulonglong2 wa = wr[0], wb2 = wr[1];
                    #pragma unroll
                    for (int j = 0; j < 3; j++) {
                        u64 hv = dupf(sh[(pb[j] + dt) * 66 + ci]);
                        fma2(acc[j][0], hv, wa.x); fma2(acc[j][1], hv, wa.y);
                        fma2(acc[j][2], hv, wb2.x); fma2(acc[j][3], hv, wb2.y);
                    }
                }
            }
            #pragma unroll
            for (int j = 0; j < 3; j++) {
                float* d = shc + rr[j] * 66 + c8;
                #pragma unroll
                for (int k = 0; k < 4; k++) {
                    float2 f = unpk(acc[j][k]);
                    d[2 * k]     = fmaxf(f.x, 0.f);
                    d[2 * k + 1] = fmaxf(f.y, 0.f);
                }
            }
        }
        __syncthreads();

        // ---- 4) k & v projections (fused) ----
        {
            u64 ak[3][4], av[3][4];
            const u64* bkk = (const u64*)(sB + 192 + c8);
            const u64* bvv = (const u64*)(sB + 256 + c8);
            #pragma unroll
            for (int j = 0; j < 3; j++)
                #pragma unroll
                for (int k = 0; k < 4; k++) { ak[j][k] = bkk[k]; av[j][k] = bvv[k]; }
            #pragma unroll 4
            for (int ci = 0; ci < C1; ci++) {
                const ulonglong2* wkr = (const ulonglong2*)(sWk + ci * C1 + c8);
                const ulonglong2* wvr = (const ulonglong2*)(sWv + ci * C1 + c8);
                ulonglong2 ka = wkr[0], kb2 = wkr[1];
                ulonglong2 va = wvr[0], vb2 = wvr[1];
                #pragma unroll
                for (int j = 0; j < 3; j++) {
                    u64 hv = dupf(shc[rr[j] * 66 + ci]);
                    fma2(ak[j][0], hv, ka.x); fma2(ak[j][1], hv, ka.y);
                    fma2(ak[j][2], hv, kb2.x); fma2(ak[j][3], hv, kb2.y);
                    fma2(av[j][0], hv, va.x); fma2(av[j][1], hv, va.y);
                    fma2(av[j][2], hv, vb2.x); fma2(av[j][3], hv, vb2.y);
                }
            }
            #pragma unroll
            for (int j = 0; j < 3; j++) {
                u64* dk = (u64*)(sk + rr[j] * 66 + c8);
                u64* dv = (u64*)(sv + rr[j] * 66 + c8);
                #pragma unroll
                for (int k = 0; k < 4; k++) { dk[k] = ak[j][k]; dv[k] = av[j][k]; }
            }
        }
        // q for last row of each seq (128 threads: s = tid>>6, c = tid&63)
        if (tid < 128) {
            int s = tid >> 6, c = tid & 63;
            float a = sB[128 + c];
            const float* hrow = shc + (s * 48 + 47) * 66;
            #pragma unroll 8
            for (int ci = 0; ci < C1; ci++) a += hrow[ci] * sWq[ci * C1 + c];
            sq[s * 64 + c] = a;
        }
        __syncthreads();

        // ---- 5) scores: 96 of them, warp w handles t = 12w..12w+11 ----
        #pragma unroll
        for (int jj = 0; jj < 12; jj++) {
            int t96 = warp * 12 + jj;
            int s = t96 >= 48;
            const float* kr = sk + t96 * 66;
            const float* qr = sq + s * 64;
            float p = qr[lane] * kr[lane] + qr[lane + 32] * kr[lane + 32];
            #pragma unroll
            for (int o = 16; o > 0; o >>= 1) p += __shfl_xor_sync(0xffffffffu, p, o);
            if (lane == 0) ss[t96] = p * 0.125f;
        }
        __syncthreads();

        // ---- 6) softmax over 48, warps 0/1 handle seqs 0/1 ----
        if (warp < 2) {
            float* sp = ss + warp * 48;
            float a  = sp[lane];
            float b2 = (lane < 16) ? sp[lane + 32] : -1e30f;
            float m = fmaxf(a, b2);
            #pragma unroll
            for (int o = 16; o > 0; o >>= 1) m = fmaxf(m, __shfl_xor_sync(0xffffffffu, m, o));
            float ea = __expf(a - m);
            float eb = (lane < 16) ? __expf(b2 - m) : 0.f;
            float sum = ea + eb;
            #pragma unroll
            for (int o = 16; o > 0; o >>= 1) sum += __shfl_xor_sync(0xffffffffu, sum, o);
            float inv = 1.f / sum;
            sp[lane] = ea * inv;
            if (lane < 16) sp[lane + 32] = eb * inv;
        }
        __syncthreads();

        // ---- 7) ctx last row -> g_last ----
        if (tid < 128) {
            int s = tid >> 6, c = tid & 63;
            const float* sp = ss + s * 48;
            const float* vb = sv + s * 48 * 66 + c;
            float a = 0.f;
            #pragma unroll
            for (int t = 0; t < T; t++) a += sp[t] * vb[t * 66];
            g_last[(size_t)(seq0 + s) * C1 + c] = a;
        }
        __syncthreads();
    }
}

// ---------------- Kernel B: MLP 64 -> 256 -> 128 -> 12 ----------------
// 16 rows per iteration, packed f32x2. W3 read from global (L1-resident, tiny).
// smem: sW1 0 (16384), sW2 16384 (32768), sb1 49152 (256), sb2 49408 (128),
//       sb3 49536 (16), sIn 49552 (16*64=1024), sZ1 50576 (16*258=4128),
//       sZ2 54704 (16*130=2080)  -> 56784 floats = 227136 bytes
#define SMEM_B_FLOATS 56784

__global__ void __launch_bounds__(256, 1)
kernelB(const float* __restrict__ W1, const float* __restrict__ b1,
        const float* __restrict__ W2, const float* __restrict__ b2,
        const float* __restrict__ W3, const float* __restrict__ b3,
        float* __restrict__ out)
{
    extern __shared__ float sm[];
    float* sW1 = sm;
    float* sW2 = sm + 16384;
    float* sb1 = sm + 49152;
    float* sb2 = sm + 49408;
    float* sb3 = sm + 49536;
    float* sIn = sm + 49552;
    float* sZ1 = sm + 50576;
    float* sZ2 = sm + 54704;

    const int tid = threadIdx.x;
    const int lane = tid & 31;
    const int warp = tid >> 5;

    for (int i = tid; i < 16384; i += 256) sW1[i] = W1[i];
    for (int i = tid; i < 32768; i += 256) sW2[i] = W2[i];
    if (tid < 256) sb1[tid] = b1[tid];
    if (tid < 128) sb2[tid] = b2[tid];
    if (tid < 12)  sb3[tid] = b3[tid];
    __syncthreads();

    // z1 mapping: warp -> colhalf ch = warp&1 (128 cols), rowblock rb = warp>>1 (4 rows)
    //             lane -> rl = lane>>4 (rows rb*4+rl, rb*4+rl+2), cl = lane&15 (8 cols)
    const int z1_col = (warp & 1) * 128 + (lane & 15) * 8;
    const int z1_r0  = (warp >> 1) * 4 + (lane >> 4);     // rows z1_r0, z1_r0+2
    // z2 mapping: warp -> colhalf h = warp>>2 (64 cols), rowblock warp&3 (4 rows)
    const int z2_col = (warp >> 2) * 64 + (lane & 7) * 8;
    const int z2_row = (warp & 3) * 4 + (lane >> 3);

    for (int base = blockIdx.x * 16; base < SEQS; base += gridDim.x * 16) {
        // stage 16 rows of g_last -> sIn [16][64]
        {
            const float4* src = (const float4*)(g_last + (size_t)base * C1);
            float4 v = src[tid];               // 256 float4 exactly = 16x64
            int row = tid >> 4, e4 = tid & 15;
            u64* d = (u64*)(sIn + row * 64 + e4 * 4);
            d[0] = pk2(v.x, v.y);
            d[1] = pk2(v.z, v.w);
        }
        __syncthreads();

        // ---- z1 = relu(in @ W1 + b1): 16 x 256 ----
        {
            u64 acc[2][4];
            const u64* bb = (const u64*)(sb1 + z1_col);
            #pragma unroll
            for (int j = 0; j < 2; j++)
                #pragma unroll
                for (int k = 0; k < 4; k++) acc[j][k] = bb[k];
            const float* in0 = sIn + z1_r0 * 64;
            const float* in1 = sIn + (z1_r0 + 2) * 64;
            #pragma unroll 8
            for (int f = 0; f < 64; f++) {
                const ulonglong2* wr = (const ulonglong2*)(sW1 + f * H1 + z1_col);
                ulonglong2 wa = wr[0], wb2 = wr[1];
                u64 x0 = dupf(in0[f]);
                u64 x1 = dupf(in1[f]);
                fma2(acc[0][0], x0, wa.x); fma2(acc[0][1], x0, wa.y);
                fma2(acc[0][2], x0, wb2.x); fma2(acc[0][3], x0, wb2.y);
                fma2(acc[1][0], x1, wa.x); fma2(acc[1][1], x1, wa.y);
                fma2(acc[1][2], x1, wb2.x); fma2(acc[1][3], x1, wb2.y);
            }
            #pragma unroll
            for (int j = 0; j < 2; j++) {
                u64* d = (u64*)(sZ1 + (z1_r0 + 2 * j) * 258 + z1_col);
                #pragma unroll
                for (int k = 0; k < 4; k++) {
                    float2 f2 = unpk(acc[j][k]);
                    d[k] = pk2(fmaxf(f2.x, 0.f), fmaxf(f2.y, 0.f));
                }
            }
        }
        __syncthreads();

        // ---- z2 = relu(z1 @ W2 + b2): 16 x 128 ----
        {
            u64 acc[4];
            const u64* bb = (const u64*)(sb2 + z2_col);
            #pragma unroll
            for (int k = 0; k < 4; k++) acc[k] = bb[k];
            const float* zr = sZ1 + z2_row * 258;
            #pragma unroll 8
            for (int f = 0; f < 256; f++) {
                const ulonglong2* wr = (const ulonglong2*)(sW2 + f * H2 + z2_col);
                ulonglong2 wa = wr[0], wb2 = wr[1];
                u64 zv = dupf(zr[f]);
                fma2(acc[0], zv, wa.x); fma2(acc[1], zv, wa.y);
                fma2(acc[2], zv, wb2.x); fma2(acc[3], zv, wb2.y);
            }
            u64* d = (u64*)(sZ2 + z2_row * 130 + z2_col);
            #pragma unroll
            for (int k = 0; k < 4; k++) {
                float2 f2 = unpk(acc[k]);
                d[k] = pk2(fmaxf(f2.x, 0.f), fmaxf(f2.y, 0.f));
            }
        }
        __syncthreads();

        // ---- pred = z2 @ W3 + b3: 16 x 12, transposed write; W3 from global ----
        if (tid < 192) {
            int r = tid / 12, p = tid % 12;
            const float* zr = sZ2 + r * 130;
            float a = sb3[p];
            #pragma unroll 16
            for (int f = 0; f < 128; f++) a += zr[f] * __ldg(&W3[f * NPRED + p]);
            int seqr = base + r;
            int bb = seqr >> 11;
            int nn = seqr & 2047;
            out[(size_t)bb * (NPRED * 2048) + p * 2048 + nn] = a;
        }
        __syncthreads();
    }
}

extern "C" void kernel_launch(void* const* d_in, const int* in_sizes, int n_in,
                              void* d_out, int out_size)
{
    const float* x     = (const float*)d_in[0];
    const float* W_in  = (const float*)d_in[1];
    const float* b_in  = (const float*)d_in[2];
    const float* W_c   = (const float*)d_in[3];
    const float* b_c   = (const float*)d_in[4];
    const float* Wq    = (const float*)d_in[5];
    const float* bq    = (const float*)d_in[6];
    const float* Wk    = (const float*)d_in[7];
    const float* bk    = (const float*)d_in[8];
    const float* Wv    = (const float*)d_in[9];
    const float* bv    = (const float*)d_in[10];
    const float* W1    = (const float*)d_in[11];
    const float* b1    = (const float*)d_in[12];
    const float* W2    = (const float*)d_in[13];
    const float* b2    = (const float*)d_in[14];
    const float* W3    = (const float*)d_in[15];
    const float* b3    = (const float*)d_in[16];

    size_t smemA = SMEM_A_FLOATS * sizeof(float);
    size_t smemB = SMEM_B_FLOATS * sizeof(float);
    cudaFuncSetAttribute(kernelA, cudaFuncAttributeMaxDynamicSharedMemorySize, (int)smemA);
    cudaFuncSetAttribute(kernelB, cudaFuncAttributeMaxDynamicSharedMemorySize, (int)smemB);

    kernelA<<<152, 256, smemA>>>(x, W_in, b_in, W_c, b_c, Wq, bq, Wk, bk, Wv, bv);
    kernelB<<<152, 256, smemB>>>(W1, b1, W2, b2, W3, b3, (float*)d_out);
}